// round 7
// baseline (speedup 1.0000x reference)
#include <cuda_runtime.h>
#include <cuda_bf16.h>
#include <cstddef>

// Problem constants
#define NN   2048
#define FF   32
#define EE   16
#define KK   32

// Scratch (no allocations allowed): node_part = nodes @ W_ne[:F],
// node_term = relu(nodes @ W_n + b_n)
__device__ float g_node_part[NN * FF];
__device__ float g_node_term[NN * FF];
// adj sink for the (defensive) fallback output layout — file scope, legal.
__device__ float g_adj_sink[NN * NN];

// ---------------------------------------------------------------------------
// Kernel 1: per-node dense matmuls (tiny: 2048x32 @ 32x32, twice).
// One warp per node row; lane f owns output feature f.
// ---------------------------------------------------------------------------
__global__ void __launch_bounds__(256) prep_kernel(
    const float* __restrict__ nodes,   // [N,F]
    const float* __restrict__ W_ne,    // [F+E, F] row-major; use rows [0,F)
    const float* __restrict__ W_n,     // [F,F]
    const float* __restrict__ b_n)     // [F]
{
    int n    = blockIdx.x * (blockDim.x >> 5) + (threadIdx.x >> 5);
    int lane = threadIdx.x & 31;
    if (n >= NN) return;

    // lane k holds nodes[n,k]
    float x = nodes[n * FF + lane];
    float a1 = 0.f, a2 = 0.f;
#pragma unroll
    for (int k = 0; k < FF; k++) {
        float xv = __shfl_sync(0xffffffffu, x, k);
        a1 = fmaf(xv, W_ne[k * FF + lane], a1);
        a2 = fmaf(xv, W_n [k * FF + lane], a2);
    }
    g_node_part[n * FF + lane] = a1;
    g_node_term[n * FF + lane] = fmaxf(a2 + b_n[lane], 0.f);
}

// ---------------------------------------------------------------------------
// Kernel 2: one block per destination row i.
//  - scans adj[i,:] (and writes it to the output adj region = fused copy)
//  - for each nonzero j: msg accumulation with relu( node_part[j] +
//    edges[i,j,:] @ W_e + b_ne ), W_e resident in smem
//  - reduce warp accumulators, apply (1+eps)*node_term + msg, then the final
//    32x32 FC (W_net) + relu, write out[i,:]
// ---------------------------------------------------------------------------
__global__ void __launch_bounds__(256) msg_kernel(
    const float* __restrict__ adj,     // [N,N]
    const float* __restrict__ edges,   // [N,N,E]
    const float* __restrict__ W_ne,    // [F+E, F]; use rows [F, F+E)
    const float* __restrict__ b_ne,    // [F]
    const float* __restrict__ W_net,   // [F,K]
    const float* __restrict__ b_net,   // [K]
    const float* __restrict__ eps,     // [1]
    float* __restrict__ out_adj,       // [N,N]  (pass-through copy)
    float* __restrict__ out_feat)      // [N,K]
{
    __shared__ float sW[EE * FF];      // W_e: 16x32 = 2 KB
    __shared__ float swacc[8][FF];     // per-warp accumulators
    __shared__ float spre[FF];

    const int i    = blockIdx.x;
    const int tid  = threadIdx.x;
    const int w    = tid >> 5;
    const int lane = tid & 31;

    // FIX (R5): EE*FF = 512 > blockDim = 256 — previous version left half of
    // sW uninitialized. Strided load covers all 512 elements.
#pragma unroll
    for (int t = tid; t < EE * FF; t += 256)
        sW[t] = W_ne[FF * FF + t];
    __syncthreads();

    const float bn = b_ne[lane];
    const size_t rowbase = (size_t)i * NN;
    float acc = 0.f;

    for (int jb = 0; jb < NN; jb += 256) {
        int j = jb + tid;
        float a = adj[rowbase + j];
        out_adj[rowbase + j] = a;                       // fused adj copy
        unsigned m = __ballot_sync(0xffffffffu, a != 0.f);
        while (m) {
            int src = __ffs(m) - 1;
            m &= m - 1;
            int jj = jb + (w << 5) + src;               // global j of this hit
            float av = __shfl_sync(0xffffffffu, a, src);
            // lanes 0..15 fetch edges[i,jj,e]; broadcast via shfl
            float ev = 0.f;
            if (lane < EE) ev = edges[(rowbase + jj) * EE + lane];
            float s = g_node_part[jj * FF + lane] + bn;
#pragma unroll
            for (int e = 0; e < EE; e++) {
                float evb = __shfl_sync(0xffffffffu, ev, e);
                s = fmaf(evb, sW[e * FF + lane], s);
            }
            acc = fmaf(av, fmaxf(s, 0.f), acc);
        }
    }

    swacc[w][lane] = acc;
    __syncthreads();

    if (w == 0) {
        float msg = 0.f;
#pragma unroll
        for (int ww = 0; ww < 8; ww++) msg += swacc[ww][lane];
        float pre = fmaf(1.f + eps[0], g_node_term[i * FF + lane], msg);
        spre[lane] = pre;
        __syncwarp();
        // out[i,k] = relu( sum_f pre[f] * W_net[f,k] + b_net[k] ), lane = k
        float o = b_net[lane];
#pragma unroll
        for (int f = 0; f < FF; f++)
            o = fmaf(spre[f], W_net[f * KK + lane], o);
        out_feat[i * KK + lane] = fmaxf(o, 0.f);
    }
}

// ---------------------------------------------------------------------------
// kernel_launch: graph-capturable, allocation-free.
// Output layout (flattened tuple): [ adj (N*N) | out (N*K) | edges (N*N*E) ]
// ---------------------------------------------------------------------------
extern "C" void kernel_launch(void* const* d_in, const int* in_sizes, int n_in,
                              void* d_out, int out_size)
{
    const float* adj    = (const float*)d_in[0];
    const float* nodes  = (const float*)d_in[1];
    const float* edges  = (const float*)d_in[2];
    const float* W_ne   = (const float*)d_in[3];
    const float* b_ne   = (const float*)d_in[4];
    const float* W_n    = (const float*)d_in[5];
    const float* b_n    = (const float*)d_in[6];
    const float* W_net  = (const float*)d_in[7];
    const float* b_net  = (const float*)d_in[8];
    const float* eps    = (const float*)d_in[9];

    float* out = (float*)d_out;

    const size_t sz_adj   = (size_t)NN * NN;
    const size_t sz_out   = (size_t)NN * KK;
    const size_t sz_edges = (size_t)NN * NN * EE;
    const size_t sz_full  = sz_adj + sz_out + sz_edges;

    float* out_adj;
    float* out_feat;
    bool full_tuple = ((size_t)out_size >= sz_full);
    if (full_tuple) {
        out_adj  = out;
        out_feat = out + sz_adj;
        // pass-through copy of edges_features (bulk of the traffic)
        cudaMemcpyAsync(out + sz_adj + sz_out, edges,
                        sz_edges * sizeof(float),
                        cudaMemcpyDeviceToDevice, 0);
    } else {
        // fallback: output holds only `out`; adj copy goes to device scratch
        cudaGetSymbolAddress((void**)&out_adj, g_adj_sink);
        out_feat = out;
    }

    // node_part / node_term
    prep_kernel<<<NN / 8, 256, 0, 0>>>(nodes, W_ne, W_n, b_n);

    msg_kernel<<<NN, 256, 0, 0>>>(adj, edges, W_ne, b_ne, W_net, b_net,
                                  eps, out_adj, out_feat);
}

// round 9
// speedup vs baseline: 1.2835x; 1.2835x over previous
#include <cuda_runtime.h>
#include <cuda_bf16.h>
#include <cstddef>

// Problem constants
#define NN   2048
#define FF   32
#define EE   16
#define KK   32

// Scratch (no allocations allowed)
__device__ float g_node_part[NN * FF];
__device__ float g_node_term[NN * FF];
// adj sink for the (defensive) fallback output layout
__device__ float g_adj_sink[NN * NN];

// ---------------------------------------------------------------------------
// Kernel 1: per-node dense matmuls (tiny). One warp per node row.
// ---------------------------------------------------------------------------
__global__ void __launch_bounds__(256) prep_kernel(
    const float* __restrict__ nodes,   // [N,F]
    const float* __restrict__ W_ne,    // [F+E, F]; rows [0,F)
    const float* __restrict__ W_n,     // [F,F]
    const float* __restrict__ b_n)     // [F]
{
    int n    = blockIdx.x * (blockDim.x >> 5) + (threadIdx.x >> 5);
    int lane = threadIdx.x & 31;
    if (n >= NN) return;

    float x = nodes[n * FF + lane];
    float a1 = 0.f, a2 = 0.f;
#pragma unroll
    for (int k = 0; k < FF; k++) {
        float xv = __shfl_sync(0xffffffffu, x, k);
        a1 = fmaf(xv, W_ne[k * FF + lane], a1);
        a2 = fmaf(xv, W_n [k * FF + lane], a2);
    }
    g_node_part[n * FF + lane] = a1;
    g_node_term[n * FF + lane] = fmaxf(a2 + b_n[lane], 0.f);
}

// ---------------------------------------------------------------------------
// Kernel 2 (fused): one block per destination row i.
//  a) stream-copies edges[i,:,:] to the output (float4, coalesced)
//  b) scans adj[i,:] with float4 + ballot (fused adj copy), computes msg over
//     the ~5% nonzero neighbors (W_e resident in smem, shfl-broadcast chain)
//  c) reduces, applies (1+eps)*node_term + msg, final 32x32 FC + relu
// ---------------------------------------------------------------------------
__global__ void __launch_bounds__(256) fused_kernel(
    const float* __restrict__ adj,     // [N,N]
    const float* __restrict__ edges,   // [N,N,E]
    const float* __restrict__ W_ne,    // [F+E, F]; rows [F, F+E)
    const float* __restrict__ b_ne,    // [F]
    const float* __restrict__ W_net,   // [F,K]
    const float* __restrict__ b_net,   // [K]
    const float* __restrict__ eps,     // [1]
    float* __restrict__ out_adj,       // [N,N]
    float* __restrict__ out_feat,      // [N,K]
    float* __restrict__ out_edges,     // [N,N,E] or nullptr
    int do_edge_copy)
{
    __shared__ float sW[EE * FF];      // W_e: 16x32 = 2 KB
    __shared__ float swacc[8][FF];
    __shared__ float spre[FF];

    const int i    = blockIdx.x;
    const int tid  = threadIdx.x;
    const int w    = tid >> 5;
    const int lane = tid & 31;

#pragma unroll
    for (int t = tid; t < EE * FF; t += 256)
        sW[t] = W_ne[FF * FF + t];
    __syncthreads();

    const size_t rowbase = (size_t)i * NN;

    // ---- (a) edges pass-through copy: 8192 float4 per row ----
    if (do_edge_copy) {
        const float4* __restrict__ e4 =
            (const float4*)(edges + rowbase * EE);
        float4* __restrict__ o4 = (float4*)(out_edges + rowbase * EE);
#pragma unroll 4
        for (int c = tid; c < (NN * EE) / 4; c += 256)
            o4[c] = e4[c];
    }

    // ---- (b) adj scan (float4) + sparse msg accumulation ----
    const float bn = b_ne[lane];
    float acc = 0.f;

    const float4* __restrict__ adj4 = (const float4*)(adj + rowbase);
    float4* __restrict__ oadj4 = (float4*)(out_adj + rowbase);

    // warp w owns j in [w*256, (w+1)*256): 2 float4 iterations of 128 j each
#pragma unroll
    for (int it = 0; it < 2; it++) {
        int c = w * 64 + it * 32 + lane;       // float4 index
        float4 a = adj4[c];
        oadj4[c] = a;                           // fused adj copy
        bool any = (a.x != 0.f) | (a.y != 0.f) | (a.z != 0.f) | (a.w != 0.f);
        unsigned m = __ballot_sync(0xffffffffu, any);
        while (m) {
            int src = __ffs(m) - 1;
            m &= m - 1;
            float ax = __shfl_sync(0xffffffffu, a.x, src);
            float ay = __shfl_sync(0xffffffffu, a.y, src);
            float az = __shfl_sync(0xffffffffu, a.z, src);
            float aw = __shfl_sync(0xffffffffu, a.w, src);
            int j0 = (w * 64 + it * 32 + src) * 4;
#pragma unroll
            for (int q = 0; q < 4; q++) {
                float av = (q == 0) ? ax : (q == 1) ? ay : (q == 2) ? az : aw;
                if (av != 0.f) {                // uniform across warp
                    int jj = j0 + q;
                    float ev = 0.f;
                    if (lane < EE)
                        ev = edges[(rowbase + jj) * EE + lane];
                    float s = g_node_part[jj * FF + lane] + bn;
#pragma unroll
                    for (int e = 0; e < EE; e++) {
                        float evb = __shfl_sync(0xffffffffu, ev, e);
                        s = fmaf(evb, sW[e * FF + lane], s);
                    }
                    acc = fmaf(av, fmaxf(s, 0.f), acc);
                }
            }
        }
    }

    swacc[w][lane] = acc;
    __syncthreads();

    // ---- (c) reduce + epilogue FC ----
    if (w == 0) {
        float msg = 0.f;
#pragma unroll
        for (int ww = 0; ww < 8; ww++) msg += swacc[ww][lane];
        float pre = fmaf(1.f + eps[0], g_node_term[i * FF + lane], msg);
        spre[lane] = pre;
        __syncwarp();
        float o = b_net[lane];
#pragma unroll
        for (int f = 0; f < FF; f++)
            o = fmaf(spre[f], W_net[f * KK + lane], o);
        out_feat[i * KK + lane] = fmaxf(o, 0.f);
    }
}

// ---------------------------------------------------------------------------
// kernel_launch: graph-capturable, allocation-free.
// Output layout: [ adj (N*N) | out (N*K) | edges (N*N*E) ]
// ---------------------------------------------------------------------------
extern "C" void kernel_launch(void* const* d_in, const int* in_sizes, int n_in,
                              void* d_out, int out_size)
{
    const float* adj    = (const float*)d_in[0];
    const float* nodes  = (const float*)d_in[1];
    const float* edges  = (const float*)d_in[2];
    const float* W_ne   = (const float*)d_in[3];
    const float* b_ne   = (const float*)d_in[4];
    const float* W_n    = (const float*)d_in[5];
    const float* b_n    = (const float*)d_in[6];
    const float* W_net  = (const float*)d_in[7];
    const float* b_net  = (const float*)d_in[8];
    const float* eps    = (const float*)d_in[9];

    float* out = (float*)d_out;

    const size_t sz_adj   = (size_t)NN * NN;
    const size_t sz_out   = (size_t)NN * KK;
    const size_t sz_edges = (size_t)NN * NN * EE;
    const size_t sz_full  = sz_adj + sz_out + sz_edges;

    float* out_adj;
    float* out_feat;
    float* out_edges;
    int    do_copy;
    if ((size_t)out_size >= sz_full) {
        out_adj   = out;
        out_feat  = out + sz_adj;
        out_edges = out + sz_adj + sz_out;
        do_copy   = 1;
    } else {
        cudaGetSymbolAddress((void**)&out_adj, g_adj_sink);
        out_feat  = out;
        out_edges = nullptr;
        do_copy   = 0;
    }

    prep_kernel<<<NN / 8, 256, 0, 0>>>(nodes, W_ne, W_n, b_n);

    fused_kernel<<<NN, 256, 0, 0>>>(adj, edges, W_ne, b_ne, W_net, b_net,
                                    eps, out_adj, out_feat, out_edges,
                                    do_copy);
}

// round 10
// speedup vs baseline: 1.3378x; 1.0423x over previous
#include <cuda_runtime.h>
#include <cuda_bf16.h>
#include <cstddef>

// Problem constants
#define NN   2048
#define FF   32
#define EE   16
#define KK   32

// Copy-role geometry: 2048 copy blocks x 256 threads cover
// N*N*E floats = 16,777,216 float4 in 32 grid-strided iterations.
#define COPY_BLOCKS   2048
#define COPY_THREADS  (COPY_BLOCKS * 256)
#define COPY_TOTAL4   ((NN * NN * EE) / 4)
#define COPY_ITERS    (COPY_TOTAL4 / COPY_THREADS)   // 32

// Scratch (no allocations allowed)
__device__ float g_node_part[NN * FF];
__device__ float g_node_term[NN * FF];
__device__ float g_adj_sink[NN * NN];   // defensive fallback sink

// ---------------------------------------------------------------------------
// Kernel 1: per-node dense matmuls (tiny). One warp per node row.
// ---------------------------------------------------------------------------
__global__ void __launch_bounds__(256) prep_kernel(
    const float* __restrict__ nodes,   // [N,F]
    const float* __restrict__ W_ne,    // [F+E, F]; rows [0,F)
    const float* __restrict__ W_n,     // [F,F]
    const float* __restrict__ b_n)     // [F]
{
    int n    = blockIdx.x * (blockDim.x >> 5) + (threadIdx.x >> 5);
    int lane = threadIdx.x & 31;
    if (n >= NN) return;

    float x = nodes[n * FF + lane];
    float a1 = 0.f, a2 = 0.f;
#pragma unroll
    for (int k = 0; k < FF; k++) {
        float xv = __shfl_sync(0xffffffffu, x, k);
        a1 = fmaf(xv, W_ne[k * FF + lane], a1);
        a2 = fmaf(xv, W_n [k * FF + lane], a2);
    }
    g_node_part[n * FF + lane] = a1;
    g_node_term[n * FF + lane] = fmaxf(a2 + b_n[lane], 0.f);
}

// ---------------------------------------------------------------------------
// Kernel 2: role-split blocks.
//  odd  bid -> pure streaming copy of edges (evict-first, keeps DRAM busy)
//  even bid -> msg row: adj scan (float4, fused copy) + sparse message +
//              (1+eps)*node_term + final 32x32 FC + relu
// Parity interleave => every wave mixes copy and msg blocks, so msg latency
// tails hide under the copy stream.
// ---------------------------------------------------------------------------
__global__ void __launch_bounds__(256) fused_kernel(
    const float* __restrict__ adj,     // [N,N]
    const float* __restrict__ edges,   // [N,N,E]
    const float* __restrict__ W_ne,    // [F+E, F]; rows [F, F+E)
    const float* __restrict__ b_ne,    // [F]
    const float* __restrict__ W_net,   // [F,K]
    const float* __restrict__ b_net,   // [K]
    const float* __restrict__ eps,     // [1]
    float* __restrict__ out_adj,       // [N,N]
    float* __restrict__ out_feat,      // [N,K]
    float* __restrict__ out_edges,     // [N,N,E] or nullptr
    int do_edge_copy)
{
    const int tid = threadIdx.x;

    // ---------------- copy role ----------------
    if (do_edge_copy && (blockIdx.x & 1)) {
        const int cb = blockIdx.x >> 1;                 // 0..2047
        const float4* __restrict__ e4 = (const float4*)edges;
        float4*       __restrict__ o4 = (float4*)out_edges;
        size_t base = (size_t)cb * 256 + tid;
#pragma unroll 4
        for (int k = 0; k < COPY_ITERS; k++) {
            size_t c = base + (size_t)k * COPY_THREADS;
            __stcs(&o4[c], __ldcs(&e4[c]));             // evict-first stream
        }
        return;
    }

    // ---------------- msg role ----------------
    const int i = do_edge_copy ? (blockIdx.x >> 1) : blockIdx.x;

    __shared__ float sW[EE * FF];      // W_e: 16x32 = 2 KB
    __shared__ float swacc[8][FF];
    __shared__ float spre[FF];

    const int w    = tid >> 5;
    const int lane = tid & 31;

#pragma unroll
    for (int t = tid; t < EE * FF; t += 256)
        sW[t] = W_ne[FF * FF + t];
    __syncthreads();

    const size_t rowbase = (size_t)i * NN;
    const float bn = b_ne[lane];
    float acc = 0.f;

    const float4* __restrict__ adj4 = (const float4*)(adj + rowbase);
    float4* __restrict__ oadj4 = (float4*)(out_adj + rowbase);

    // warp w owns j in [w*256, (w+1)*256): 2 float4 iterations of 128 j each
#pragma unroll
    for (int it = 0; it < 2; it++) {
        int c = w * 64 + it * 32 + lane;       // float4 index
        float4 a = adj4[c];
        oadj4[c] = a;                           // fused adj copy
        bool any = (a.x != 0.f) | (a.y != 0.f) | (a.z != 0.f) | (a.w != 0.f);
        unsigned m = __ballot_sync(0xffffffffu, any);
        while (m) {
            int src = __ffs(m) - 1;
            m &= m - 1;
            float ax = __shfl_sync(0xffffffffu, a.x, src);
            float ay = __shfl_sync(0xffffffffu, a.y, src);
            float az = __shfl_sync(0xffffffffu, a.z, src);
            float aw = __shfl_sync(0xffffffffu, a.w, src);
            int j0 = (w * 64 + it * 32 + src) * 4;
#pragma unroll
            for (int q = 0; q < 4; q++) {
                float av = (q == 0) ? ax : (q == 1) ? ay : (q == 2) ? az : aw;
                if (av != 0.f) {                // uniform across warp
                    int jj = j0 + q;
                    float ev = 0.f;
                    if (lane < EE)
                        ev = edges[(rowbase + jj) * EE + lane];
                    float s = g_node_part[jj * FF + lane] + bn;
#pragma unroll
                    for (int e = 0; e < EE; e++) {
                        float evb = __shfl_sync(0xffffffffu, ev, e);
                        s = fmaf(evb, sW[e * FF + lane], s);
                    }
                    acc = fmaf(av, fmaxf(s, 0.f), acc);
                }
            }
        }
    }

    swacc[w][lane] = acc;
    __syncthreads();

    if (w == 0) {
        float msg = 0.f;
#pragma unroll
        for (int ww = 0; ww < 8; ww++) msg += swacc[ww][lane];
        float pre = fmaf(1.f + eps[0], g_node_term[i * FF + lane], msg);
        spre[lane] = pre;
        __syncwarp();
        float o = b_net[lane];
#pragma unroll
        for (int f = 0; f < FF; f++)
            o = fmaf(spre[f], W_net[f * KK + lane], o);
        out_feat[i * KK + lane] = fmaxf(o, 0.f);
    }
}

// ---------------------------------------------------------------------------
// kernel_launch: graph-capturable, allocation-free.
// Output layout: [ adj (N*N) | out (N*K) | edges (N*N*E) ]
// ---------------------------------------------------------------------------
extern "C" void kernel_launch(void* const* d_in, const int* in_sizes, int n_in,
                              void* d_out, int out_size)
{
    const float* adj    = (const float*)d_in[0];
    const float* nodes  = (const float*)d_in[1];
    const float* edges  = (const float*)d_in[2];
    const float* W_ne   = (const float*)d_in[3];
    const float* b_ne   = (const float*)d_in[4];
    const float* W_n    = (const float*)d_in[5];
    const float* b_n    = (const float*)d_in[6];
    const float* W_net  = (const float*)d_in[7];
    const float* b_net  = (const float*)d_in[8];
    const float* eps    = (const float*)d_in[9];

    float* out = (float*)d_out;

    const size_t sz_adj   = (size_t)NN * NN;
    const size_t sz_out   = (size_t)NN * KK;
    const size_t sz_edges = (size_t)NN * NN * EE;
    const size_t sz_full  = sz_adj + sz_out + sz_edges;

    float* out_adj;
    float* out_feat;
    float* out_edges;
    int    do_copy;
    if ((size_t)out_size >= sz_full) {
        out_adj   = out;
        out_feat  = out + sz_adj;
        out_edges = out + sz_adj + sz_out;
        do_copy   = 1;
    } else {
        cudaGetSymbolAddress((void**)&out_adj, g_adj_sink);
        out_feat  = out;
        out_edges = nullptr;
        do_copy   = 0;
    }

    prep_kernel<<<NN / 8, 256, 0, 0>>>(nodes, W_ne, W_n, b_n);

    int grid = do_copy ? (NN + COPY_BLOCKS) : NN;   // 4096 role-split blocks
    fused_kernel<<<grid, 256, 0, 0>>>(adj, edges, W_ne, b_ne, W_net, b_net,
                                      eps, out_adj, out_feat, out_edges,
                                      do_copy);
}

// round 14
// speedup vs baseline: 1.5110x; 1.1294x over previous
#include <cuda_runtime.h>
#include <cuda_bf16.h>
#include <cstddef>
#include <cstdint>

// Problem constants
#define NN   2048
#define FF   32
#define EE   16
#define KK   32

// Copy-role geometry: 2048 copy blocks, each owns a CONTIGUOUS 128 KiB slice
// of the 256 MiB edges tensor, streamed via a 4-stage x 4 KiB cp.async.bulk
// ring with lookahead 2 (single driver thread, zero register pressure).
#define COPY_BLOCKS   2048
#define CHUNK_BYTES   4096
#define NCHUNK        32                 // 32 * 4 KiB = 128 KiB per block
#define NSTAGE        4
#define LOOKAHEAD     2

// Scratch (no allocations allowed)
__device__ float g_node_part[NN * FF];
__device__ float g_node_term[NN * FF];
__device__ float g_adj_sink[NN * NN];   // defensive fallback sink

// ---- minimal PTX helpers (1D bulk copy + mbarrier) ----
static __device__ __forceinline__ uint32_t smem_u32(const void* p) {
    uint32_t a;
    asm("{ .reg .u64 t; cvta.to.shared.u64 t, %1; cvt.u32.u64 %0, t; }"
        : "=r"(a) : "l"(p));
    return a;
}
#define MBAR_INIT(addr, cnt) \
    asm volatile("mbarrier.init.shared.b64 [%0], %1;" :: "r"(addr), "r"(cnt) : "memory")
#define MBAR_EXPECT_TX(addr, bytes) \
    asm volatile("mbarrier.arrive.expect_tx.shared.b64 _, [%0], %1;" \
                 :: "r"(addr), "r"(bytes) : "memory")
#define BULK_G2S(smem, gmem, bytes, mbar) \
    asm volatile("cp.async.bulk.shared::cta.global.mbarrier::complete_tx::bytes " \
                 "[%0], [%1], %2, [%3];" \
                 :: "r"(smem), "l"(gmem), "r"(bytes), "r"(mbar) : "memory")
#define BULK_S2G(gmem, smem, bytes) \
    asm volatile("cp.async.bulk.global.shared::cta.bulk_group [%0], [%1], %2;" \
                 :: "l"(gmem), "r"(smem), "r"(bytes) : "memory")
static __device__ __forceinline__ void mbar_wait_parity(uint32_t mbar, uint32_t parity) {
    asm volatile(
        "{\n\t"
        ".reg .pred P1;\n\t"
        "WAIT_LOOP_%=:\n\t"
        "mbarrier.try_wait.parity.acquire.cta.shared::cta.b64 P1, [%0], %1, 0x989680;\n\t"
        "@P1 bra.uni WAIT_DONE_%=;\n\t"
        "bra.uni WAIT_LOOP_%=;\n\t"
        "WAIT_DONE_%=:\n\t"
        "}"
        :: "r"(mbar), "r"(parity) : "memory");
}

// Shared-memory overlay: copy role and msg role never coexist in a block,
// so union them to keep smem/block small (occupancy stays reg-limited at 8).
struct SmemCopy {
    char     buf[NSTAGE][CHUNK_BYTES];   // 16 KiB staging ring
    uint64_t mbar[NSTAGE];
};
struct SmemMsg {
    float sW[EE * FF];                   // W_e: 16x32 = 2 KB
    float swacc[8][FF];
    float spre[FF];
};
union SmemU {
    SmemCopy c;
    SmemMsg  m;
};

// ---------------------------------------------------------------------------
// Kernel 1: per-node dense matmuls (tiny). One warp per node row.
// ---------------------------------------------------------------------------
__global__ void __launch_bounds__(256) prep_kernel(
    const float* __restrict__ nodes,   // [N,F]
    const float* __restrict__ W_ne,    // [F+E, F]; rows [0,F)
    const float* __restrict__ W_n,     // [F,F]
    const float* __restrict__ b_n)     // [F]
{
    int n    = blockIdx.x * (blockDim.x >> 5) + (threadIdx.x >> 5);
    int lane = threadIdx.x & 31;
    if (n >= NN) return;

    float x = nodes[n * FF + lane];
    float a1 = 0.f, a2 = 0.f;
#pragma unroll
    for (int k = 0; k < FF; k++) {
        float xv = __shfl_sync(0xffffffffu, x, k);
        a1 = fmaf(xv, W_ne[k * FF + lane], a1);
        a2 = fmaf(xv, W_n [k * FF + lane], a2);
    }
    g_node_part[n * FF + lane] = a1;
    g_node_term[n * FF + lane] = fmaxf(a2 + b_n[lane], 0.f);
}

// ---------------------------------------------------------------------------
// Kernel 2: role-split blocks (parity interleave).
//  odd  bid -> edges copy via cp.async.bulk 4-stage ring (1 driver thread)
//  even bid -> msg row: adj scan (float4, fused copy) + sparse message +
//              (1+eps)*node_term + final 32x32 FC + relu
// ---------------------------------------------------------------------------
__global__ void __launch_bounds__(256) fused_kernel(
    const float* __restrict__ adj,     // [N,N]
    const float* __restrict__ edges,   // [N,N,E]
    const float* __restrict__ W_ne,    // [F+E, F]; rows [F, F+E)
    const float* __restrict__ b_ne,    // [F]
    const float* __restrict__ W_net,   // [F,K]
    const float* __restrict__ b_net,   // [K]
    const float* __restrict__ eps,     // [1]
    float* __restrict__ out_adj,       // [N,N]
    float* __restrict__ out_feat,      // [N,K]
    float* __restrict__ out_edges,     // [N,N,E] or nullptr
    int do_edge_copy)
{
    __shared__ __align__(128) SmemU su;

    const int tid = threadIdx.x;

    // ---------------- copy role ----------------
    if (do_edge_copy && (blockIdx.x & 1)) {
        if (tid == 0) {
            const uint32_t sb = smem_u32(&su.c.buf[0][0]);
            uint32_t mb[NSTAGE];
#pragma unroll
            for (int s = 0; s < NSTAGE; s++) {
                mb[s] = smem_u32(&su.c.mbar[s]);
                MBAR_INIT(mb[s], 1);
            }
            asm volatile("fence.proxy.async.shared::cta;" ::: "memory");

            const int cb = blockIdx.x >> 1;                 // 0..2047
            const char* __restrict__ src =
                (const char*)edges + (size_t)cb * CHUNK_BYTES * NCHUNK;
            char* __restrict__ dst =
                (char*)out_edges + (size_t)cb * CHUNK_BYTES * NCHUNK;

            // prologue: loads for chunks 0..LOOKAHEAD-1
#pragma unroll
            for (int c = 0; c < LOOKAHEAD; c++) {
                MBAR_EXPECT_TX(mb[c], CHUNK_BYTES);
                BULK_G2S(sb + (uint32_t)c * CHUNK_BYTES,
                         src + (size_t)c * CHUNK_BYTES, CHUNK_BYTES, mb[c]);
            }

            uint32_t ph[NSTAGE] = {0, 0, 0, 0};
            for (int c = 0; c < NCHUNK; c++) {
                const int s = c & (NSTAGE - 1);
                // issue load for chunk c+LOOKAHEAD
                if (c + LOOKAHEAD < NCHUNK) {
                    const int s2 = (c + LOOKAHEAD) & (NSTAGE - 1);
                    if (c + LOOKAHEAD >= NSTAGE) {
                        // stage s2 last used by chunk c+LOOKAHEAD-NSTAGE = c-2;
                        // its store is the 2nd-most-recent committed group.
                        // read 1 => all but the most recent store are read-done.
                        asm volatile("cp.async.bulk.wait_group.read 1;"
                                     ::: "memory");
                    }
                    MBAR_EXPECT_TX(mb[s2], CHUNK_BYTES);
                    BULK_G2S(sb + (uint32_t)s2 * CHUNK_BYTES,
                             src + (size_t)(c + LOOKAHEAD) * CHUNK_BYTES,
                             CHUNK_BYTES, mb[s2]);
                }
                // wait chunk c's load, then stream it back out
                mbar_wait_parity(mb[s], ph[s]);
                ph[s] ^= 1;
                BULK_S2G(dst + (size_t)c * CHUNK_BYTES,
                         sb + (uint32_t)s * CHUNK_BYTES, CHUNK_BYTES);
                asm volatile("cp.async.bulk.commit_group;" ::: "memory");
            }
            asm volatile("cp.async.bulk.wait_group 0;" ::: "memory");
        }
        return;
    }

    // ---------------- msg role ----------------
    const int i = do_edge_copy ? (blockIdx.x >> 1) : blockIdx.x;

    const int w    = tid >> 5;
    const int lane = tid & 31;

#pragma unroll
    for (int t = tid; t < EE * FF; t += 256)
        su.m.sW[t] = W_ne[FF * FF + t];
    __syncthreads();

    const size_t rowbase = (size_t)i * NN;
    const float bn = b_ne[lane];
    float acc = 0.f;

    const float4* __restrict__ adj4 = (const float4*)(adj + rowbase);
    float4* __restrict__ oadj4 = (float4*)(out_adj + rowbase);

    // warp w owns j in [w*256, (w+1)*256): 2 float4 iterations of 128 j each
#pragma unroll
    for (int it = 0; it < 2; it++) {
        int c = w * 64 + it * 32 + lane;       // float4 index
        float4 a = adj4[c];
        oadj4[c] = a;                           // fused adj copy
        bool any = (a.x != 0.f) | (a.y != 0.f) | (a.z != 0.f) | (a.w != 0.f);
        unsigned m = __ballot_sync(0xffffffffu, any);
        while (m) {
            int src = __ffs(m) - 1;
            m &= m - 1;
            float ax = __shfl_sync(0xffffffffu, a.x, src);
            float ay = __shfl_sync(0xffffffffu, a.y, src);
            float az = __shfl_sync(0xffffffffu, a.z, src);
            float aw = __shfl_sync(0xffffffffu, a.w, src);
            int j0 = (w * 64 + it * 32 + src) * 4;
#pragma unroll
            for (int q = 0; q < 4; q++) {
                float av = (q == 0) ? ax : (q == 1) ? ay : (q == 2) ? az : aw;
                if (av != 0.f) {                // uniform across warp
                    int jj = j0 + q;
                    float ev = 0.f;
                    if (lane < EE)
                        ev = edges[(rowbase + jj) * EE + lane];
                    float s = g_node_part[jj * FF + lane] + bn;
#pragma unroll
                    for (int e = 0; e < EE; e++) {
                        float evb = __shfl_sync(0xffffffffu, ev, e);
                        s = fmaf(evb, su.m.sW[e * FF + lane], s);
                    }
                    acc = fmaf(av, fmaxf(s, 0.f), acc);
                }
            }
        }
    }

    su.m.swacc[w][lane] = acc;
    __syncthreads();

    if (w == 0) {
        float msg = 0.f;
#pragma unroll
        for (int ww = 0; ww < 8; ww++) msg += su.m.swacc[ww][lane];
        float pre = fmaf(1.f + eps[0], g_node_term[i * FF + lane], msg);
        su.m.spre[lane] = pre;
        __syncwarp();
        float o = b_net[lane];
#pragma unroll
        for (int f = 0; f < FF; f++)
            o = fmaf(su.m.spre[f], W_net[f * KK + lane], o);
        out_feat[i * KK + lane] = fmaxf(o, 0.f);
    }
}

// ---------------------------------------------------------------------------
// kernel_launch: graph-capturable, allocation-free.
// Output layout: [ adj (N*N) | out (N*K) | edges (N*N*E) ]
// ---------------------------------------------------------------------------
extern "C" void kernel_launch(void* const* d_in, const int* in_sizes, int n_in,
                              void* d_out, int out_size)
{
    const float* adj    = (const float*)d_in[0];
    const float* nodes  = (const float*)d_in[1];
    const float* edges  = (const float*)d_in[2];
    const float* W_ne   = (const float*)d_in[3];
    const float* b_ne   = (const float*)d_in[4];
    const float* W_n    = (const float*)d_in[5];
    const float* b_n    = (const float*)d_in[6];
    const float* W_net  = (const float*)d_in[7];
    const float* b_net  = (const float*)d_in[8];
    const float* eps    = (const float*)d_in[9];

    float* out = (float*)d_out;

    const size_t sz_adj   = (size_t)NN * NN;
    const size_t sz_out   = (size_t)NN * KK;
    const size_t sz_edges = (size_t)NN * NN * EE;
    const size_t sz_full  = sz_adj + sz_out + sz_edges;

    float* out_adj;
    float* out_feat;
    float* out_edges;
    int    do_copy;
    if ((size_t)out_size >= sz_full) {
        out_adj   = out;
        out_feat  = out + sz_adj;
        out_edges = out + sz_adj + sz_out;
        do_copy   = 1;
    } else {
        cudaGetSymbolAddress((void**)&out_adj, g_adj_sink);
        out_feat  = out;
        out_edges = nullptr;
        do_copy   = 0;
    }

    prep_kernel<<<NN / 8, 256, 0, 0>>>(nodes, W_ne, W_n, b_n);

    int grid = do_copy ? (NN + COPY_BLOCKS) : NN;   // 4096 role-split blocks
    fused_kernel<<<grid, 256, 0, 0>>>(adj, edges, W_ne, b_ne, W_net, b_net,
                                      eps, out_adj, out_feat, out_edges,
                                      do_copy);
}